// round 16
// baseline (speedup 1.0000x reference)
#include <cuda_runtime.h>
#include <cuda_bf16.h>
#include <cstdint>

#define B_   64
#define T_   512
#define H_   512
#define E_   128
#define C_   1000
#define G7   (7 * H_)    // 3584
#define OUTW (6 * H_)    // 3072
#define NCTA 128
#define NTHR 608         // 16 MMA warps + 1 producer warp + 2 epilogue warps

typedef unsigned long long ull;

// ---- device-global scratch ----
__device__ float g_tg[C_ * G7];                               // table_gates (14.3 MB)
__device__ __align__(128) unsigned char g_himg[4][2][32768];  // [quarter][parity] A-image (fragment order)
__device__ int           g_count;
__device__ volatile int  g_sense;
__device__ int           g_cnt[16];                           // [quarter*4 + group] cumulative publish counters

// ---- math helpers ----
__device__ __forceinline__ float sigf(float x)      { return 1.0f / (1.0f + expf(-x)); }
__device__ __forceinline__ float softplusf(float x) { return fmaxf(x, 0.0f) + log1pf(expf(-fabsf(x))); }

__device__ __forceinline__ uint32_t smem_u32(const void* p)
{
    uint32_t a;
    asm("{ .reg .u64 t; cvta.to.shared.u64 t, %1; cvt.u32.u64 %0, t; }" : "=r"(a) : "l"(p));
    return a;
}
__device__ __forceinline__ int ld_acq(const int* p)
{
    int v;
    asm volatile("ld.acquire.gpu.global.s32 %0, [%1];" : "=r"(v) : "l"(p) : "memory");
    return v;
}
__device__ __forceinline__ void mbar_init(uint32_t mbar, uint32_t cnt)
{
    asm volatile("mbarrier.init.shared.b64 [%0], %1;" :: "r"(mbar), "r"(cnt) : "memory");
}
__device__ __forceinline__ void mbar_expect_tx(uint32_t mbar, uint32_t bytes)
{
    asm volatile("mbarrier.arrive.expect_tx.shared.b64 _, [%0], %1;" :: "r"(mbar), "r"(bytes) : "memory");
}
__device__ __forceinline__ void mbar_arrive(uint32_t mbar)
{
    asm volatile("mbarrier.arrive.release.cta.shared::cta.b64 _, [%0];" :: "r"(mbar) : "memory");
}
__device__ __forceinline__ void bulk_ldgsts(uint32_t dst, const void* src, uint32_t bytes, uint32_t mbar)
{
    asm volatile("cp.async.bulk.shared::cta.global.mbarrier::complete_tx::bytes [%0], [%1], %2, [%3];"
                 :: "r"(dst), "l"(src), "r"(bytes), "r"(mbar) : "memory");
}
__device__ __forceinline__ void mbar_wait(uint32_t mbar, uint32_t parity)
{
    uint32_t done;
    asm volatile(
        "{\n\t.reg .pred p;\n\t"
        "mbarrier.try_wait.parity.acquire.cta.shared::cta.b64 p, [%1], %2;\n\t"
        "selp.b32 %0, 1, 0, p;\n\t}"
        : "=r"(done) : "r"(mbar), "r"(parity) : "memory");
    if (!done) {
        asm volatile(
            "{\n\t.reg .pred P1;\n\t"
            "WL_%=:\n\t"
            "mbarrier.try_wait.parity.acquire.cta.shared::cta.b64 P1, [%0], %1, 0x989680;\n\t"
            "@P1 bra.uni WD_%=;\n\t"
            "bra.uni WL_%=;\n\t"
            "WD_%=:\n\t}"
            :: "r"(mbar), "r"(parity) : "memory");
    }
}
__device__ __forceinline__ void fence_proxy_async_()
{
    asm volatile("fence.proxy.async;" ::: "memory");
}

// bf16 mma.sync (baseline PTX, sm_80+)
__device__ __forceinline__ void mma16816(float* d,
                                         uint32_t a0, uint32_t a1, uint32_t a2, uint32_t a3,
                                         uint32_t b0, uint32_t b1)
{
    asm volatile(
        "mma.sync.aligned.m16n8k16.row.col.f32.bf16.bf16.f32 "
        "{%0,%1,%2,%3}, {%4,%5,%6,%7}, {%8,%9}, {%0,%1,%2,%3};"
        : "+f"(d[0]), "+f"(d[1]), "+f"(d[2]), "+f"(d[3])
        : "r"(a0), "r"(a1), "r"(a2), "r"(a3), "r"(b0), "r"(b1));
}

// ---- smem layout (bytes) ----
#define A_OFF      0                  // 4 quarter A buffers x 32KB = 131072
#define WF_OFF     131072             // W fragments: 64KB
#define EXCH_OFF   196608             // 8 x 32 x 29 fp32 = 29696
#define MBAR_OFF   226304             // full[4][4] + consumed[4] + ready + free
#define SMEM_BYTES (MBAR_OFF + 256)   // 226560

// quarter A-image offset for element (m in 0..31, k in 0..511); chunk c = kt in [8c,8c+8) = 8KB
__device__ __forceinline__ uint32_t aimg_off(int m, int k)
{
    int mt = m >> 4, mr = m & 15;
    int kt = k >> 4, kr = k & 15;
    int lane = ((mr & 7) << 2) | ((kr >> 1) & 3);
    int reg  = ((mr >> 3) & 1) | ((kr & 8) ? 2 : 0);
    return ((((uint32_t)(kt * 2 + mt) * 32 + lane) * 4 + reg) * 4) + ((kr & 1) * 2);
}

// atomic grid sync (init only; called twice -> even parity per launch, replay safe)
__device__ __forceinline__ void grid_sync_init(int* sense)
{
    __threadfence();
    __syncthreads();
    if (threadIdx.x == 0) {
        int s = *sense ^ 1;
        *sense = s;
        if (atomicAdd(&g_count, 1) == (int)gridDim.x - 1) {
            g_count = 0;
            __threadfence();
            g_sense = s;
        } else {
            while (g_sense != s) { __nanosleep(64); }
            __threadfence();
        }
    }
    __syncthreads();
}

// =====================  Kernel 1: table_gates  =====================
__global__ void tg_kernel(const float* __restrict__ emb,
                          const float* __restrict__ W,
                          const float* __restrict__ bias)
{
    __shared__ float sh_e[16][E_];
    const int col = blockIdx.x * 256 + threadIdx.x;
    const int c0  = blockIdx.y * 16;

    for (int i = threadIdx.x; i < 16 * E_; i += 256) {
        int ci = i >> 7, e = i & 127;
        int c  = c0 + ci;
        sh_e[ci][e] = (c < C_) ? emb[c * E_ + e] : 0.0f;
    }
    __syncthreads();

    float acc[16];
#pragma unroll
    for (int i = 0; i < 16; ++i) acc[i] = 0.0f;

    for (int e = 0; e < E_; ++e) {
        float wv = W[e * G7 + col];
#pragma unroll
        for (int i = 0; i < 16; ++i) acc[i] = fmaf(sh_e[i][e], wv, acc[i]);
    }
    float bb = bias[col];
#pragma unroll
    for (int i = 0; i < 16; ++i) {
        int c = c0 + i;
        if (c < C_) g_tg[c * G7 + col] = acc[i] + bb;
    }
}

// =====================  Kernel 2: warp-specialized HMMA, 4 quarter chains  =====================
// Warps 0..15 (MMA): mt = wid & 1, kq = wid >> 1 (kt in [4kq, 4kq+4), chunk c = kq>>1).
// Thread 512 (producer): polls counters, issues TMA for quarter qt step t.
// Warps 17,18 (epilogue, tid 544..607): gates + publish + counter bump.
// mbarriers: full[qt][c] = mb+(qt*4+c)*8 ; consumed[qt] = mb+128+qt*8 ;
//            exch_ready = mb+160 (16 arr) ; exch_free = mb+168 (64 arr).
__global__ void __launch_bounds__(NTHR, 1)
rec_kernel(const int*   __restrict__ marks,
           const float* __restrict__ ts,
           const float* __restrict__ Wc,
           const float* __restrict__ init,
           float*       __restrict__ out)
{
    extern __shared__ unsigned char smem[];
    uint32_t*      wf   = (uint32_t*)(smem + WF_OFF);
    float*         exch = (float*)(smem + EXCH_OFF);     // [kq8][32][29]
    const uint32_t mb   = smem_u32(smem + MBAR_OFF);
    const uint32_t smA0 = smem_u32(smem + A_OFF);

    const int tid  = threadIdx.x;
    const int cta  = blockIdx.x;
    const int lane = tid & 31;
    const int wid  = tid >> 5;

    if (tid == 0) {
#pragma unroll
        for (int i = 0; i < 16; ++i) mbar_init(mb + i * 8, 1);        // full
#pragma unroll
        for (int i = 0; i < 4; ++i) mbar_init(mb + 128 + i * 8, 16);  // consumed
        mbar_init(mb + 160, 16);                                      // exch_ready
        mbar_init(mb + 168, 64);                                      // exch_free
    }
    if (cta == 0 && tid < 16) g_cnt[tid] = 0;

    // ---- prepack W fragments (hi pass 0 / lo pass 1), B-fragment order ----
    for (int idx = tid; idx < 8192; idx += NTHR) {
        int l    = idx & 31;
        int nt   = (idx >> 5) & 3;
        int kt   = (idx >> 7) & 31;
        int pass = idx >> 12;
        int n    = nt * 8 + (l >> 2);
        int k0   = kt * 16 + (l & 3) * 2;
        float w[4];
#pragma unroll
        for (int i = 0; i < 4; ++i) {
            int k = k0 + (i & 1) + ((i >> 1) * 8);
            float v = 0.0f;
            if (n < 28) v = Wc[(size_t)(E_ + k) * G7 + (n >> 2) * H_ + cta * 4 + (n & 3)];
            if (pass == 0) w[i] = __bfloat162float(__float2bfloat16(v));
            else           w[i] = v - __bfloat162float(__float2bfloat16(v));
        }
        __nv_bfloat162 r0, r1;
        r0.x = __float2bfloat16(w[0]); r0.y = __float2bfloat16(w[1]);
        r1.x = __float2bfloat16(w[2]); r1.y = __float2bfloat16(w[3]);
        wf[idx * 2]     = *(uint32_t*)&r0;
        wf[idx * 2 + 1] = *(uint32_t*)&r1;
    }

    // ---- init h images t=0 ----
    for (int idx = tid; idx < 512; idx += NTHR) {
        int b    = idx >> 3;
        int jj   = (idx >> 1) & 3;
        int hilo = idx & 1;
        int k    = cta * 4 + jj;
        float v  = tanhf(init[k]);
        __nv_bfloat16 hi = __float2bfloat16(v);
        __nv_bfloat16 val = hilo ? __float2bfloat16(v - __bfloat162float(hi)) : hi;
        int qt = b >> 4;
        int m  = (b & 15) + hilo * 16;
        *(__nv_bfloat16*)(g_himg[qt][0] + aimg_off(m, k)) = val;
    }

    // ---- output row t=0 ----
    for (int idx = tid; idx < 4 * 6 * 64; idx += NTHR) {
        int bb = idx & 63; int rest = idx >> 6;
        int f = rest % 6; int jj = rest / 6;
        int jg = cta * 4 + jj;
        float v;
        switch (f) {
            case 0:  v = tanhf(init[0 * H_ + jg]);     break;
            case 1:  v = sigf (init[5 * H_ + jg]);     break;
            case 2:  v = tanhf(init[2 * H_ + jg]);     break;
            case 3:  v = tanhf(init[3 * H_ + jg]);     break;
            case 4:  v = softplusf(init[4 * H_ + jg]); break;
            default: v = tanhf(init[1 * H_ + jg]);     break;
        }
        out[(size_t)bb * (513 * OUTW) + f * H_ + jg] = v;
    }

    // ---- two init grid syncs (h0/counters visible; even parity) ----
    int sense = 0;
    grid_sync_init(&sense);
    grid_sync_init(&sense);

    // =====================  producer (tid 512)  =====================
    if (wid == 16) {
        if (lane != 0) return;
        int phc[4] = {0, 0, 0, 0};
        fence_proxy_async_();
#pragma unroll
        for (int qt = 0; qt < 4; ++qt) {
#pragma unroll
            for (int c = 0; c < 4; ++c) {
                mbar_expect_tx(mb + (qt * 4 + c) * 8, 8192);
                bulk_ldgsts(smA0 + qt * 32768 + c * 8192, g_himg[qt][0] + c * 8192, 8192, mb + (qt * 4 + c) * 8);
            }
        }
        for (int sp = 4; sp < 2048; ++sp) {
            const int qt = sp & 3;
            const int t  = sp >> 2;
            mbar_wait(mb + 128 + qt * 8, phc[qt]); phc[qt] ^= 1;   // prev A buffer consumed
            const int need = 32 * t;
#pragma unroll
            for (int c = 0; c < 4; ++c) {
                while (ld_acq(&g_cnt[qt * 4 + c]) < need) { __nanosleep(32); }
            }
            fence_proxy_async_();
            const unsigned char* src = g_himg[qt][t & 1];
            const uint32_t dstb = smA0 + qt * 32768;
#pragma unroll
            for (int c = 0; c < 4; ++c) {
                mbar_expect_tx(mb + (qt * 4 + c) * 8, 8192);
                bulk_ldgsts(dstb + c * 8192, src + c * 8192, 8192, mb + (qt * 4 + c) * 8);
            }
        }
        return;
    }

    // =====================  epilogue warps (tid 544..607)  =====================
    if (wid >= 17) {
        const int et   = tid - 544;         // 0..63
        const int eb16 = et >> 2;
        const int ejl  = et & 3;
        const int ej   = cta * 4 + ejl;
        const int grpN = cta >> 5;

        float cdv[4], cbv[4];
#pragma unroll
        for (int q = 0; q < 4; ++q) { cdv[q] = tanhf(init[H_ + ej]); cbv[q] = tanhf(init[2 * H_ + ej]); }

        const uint32_t off_hi = aimg_off(eb16, ej);
        const uint32_t off_lo = aimg_off(eb16 + 16, ej);

        int ph_ready = 0;
        for (int sp = 0; sp < 2048; ++sp) {
            const int qt = sp & 3;
            const int t  = sp >> 2;
            const int b  = qt * 16 + eb16;

            // prefetch (independent of exch)
            int   mk  = __ldg(&marks[b * T_ + t]);
            float tsv = __ldg(&ts[b * T_ + t]);
            float tsp = (t > 0) ? __ldg(&ts[b * T_ + t - 1]) : 0.0f;
            const float* tgp = g_tg + (size_t)mk * G7 + ej;
            float tgv[7];
#pragma unroll
            for (int g = 0; g < 7; ++g) tgv[g] = __ldcg(tgp + g * H_);

            mbar_wait(mb + 160, ph_ready); ph_ready ^= 1;

            float a[7];
#pragma unroll
            for (int g = 0; g < 7; ++g) {
                int n = g * 4 + ejl;
                float s = 0.f;
#pragma unroll
                for (int kq = 0; kq < 8; ++kq)
                    s += exch[kq * (32 * 29) + eb16 * 29 + n]
                       + exch[kq * (32 * 29) + (eb16 + 16) * 29 + n];
                a[g] = s;
            }
            mbar_arrive(mb + 168);   // exch free (64 arrivals)

            float dur = tsv - tsp;
            float gi  = sigf (a[0] + tgv[0]);
            float gf  = sigf (a[1] + tgv[1]);
            float gz  = tanhf(a[2] + tgv[2]);
            float go  = sigf (a[3] + tgv[3]);
            float gib = sigf (a[4] + tgv[4]);
            float gfb = sigf (a[5] + tgv[5]);
            float gd  = softplusf(a[6] + tgv[6]);

            float cx  = gf * cdv[qt] + gi * gz;
            float cbx = gfb * cbv[qt] + gib * gz;
            float cd  = cbx + (cx - cbx) * expf(-gd * dur);
            float hd  = go * tanhf(cd);
            cdv[qt] = cd; cbv[qt] = cbx;

            __nv_bfloat16 hi = __float2bfloat16(hd);
            __nv_bfloat16 lo = __float2bfloat16(hd - __bfloat162float(hi));
            unsigned char* dst = g_himg[qt][(t + 1) & 1];
            *(__nv_bfloat16*)(dst + off_hi) = hi;
            *(__nv_bfloat16*)(dst + off_lo) = lo;

            __threadfence();
            asm volatile("bar.sync 3, 64;" ::: "memory");
            if (et == 0) atomicAdd(&g_cnt[qt * 4 + grpN], 1);

            // off critical path: fp32 outputs
            size_t ob = (size_t)b * (513 * OUTW) + (size_t)(t + 1) * OUTW + ej;
            out[ob]          = hd;
            out[ob + 1 * H_] = go;
            out[ob + 2 * H_] = cbx;
            out[ob + 3 * H_] = cx;
            out[ob + 4 * H_] = gd;
            out[ob + 5 * H_] = cd;
        }
        return;
    }

    // =====================  MMA warps (tid < 512)  =====================
    {
        const int mt  = wid & 1;
        const int kq  = wid >> 1;        // 0..7
        const int c   = kq >> 1;         // chunk id
        const int grp = lane >> 2;
        const int tg4 = lane & 3;

        int ph_free = 0;
        for (int sp = 0; sp < 2048; ++sp) {
            const int qt = sp & 3;
            const int t  = sp >> 2;

            mbar_wait(mb + (qt * 4 + c) * 8, t & 1);

            float acc[4][4];
#pragma unroll
            for (int j = 0; j < 4; ++j)
#pragma unroll
                for (int q = 0; q < 4; ++q) acc[j][q] = 0.0f;

            const uint32_t abase = smA0 + qt * 32768 + (uint32_t)(mt * 32 + lane) * 16;
#pragma unroll
            for (int kti = 0; kti < 4; ++kti) {
                const int kt = kq * 4 + kti;
                uint32_t a0, a1, a2, a3;
                asm volatile("ld.shared.v4.b32 {%0,%1,%2,%3}, [%4];"
                             : "=r"(a0), "=r"(a1), "=r"(a2), "=r"(a3)
                             : "r"(abase + (uint32_t)kt * 1024));
#pragma unroll
                for (int pass = 0; pass < 2; ++pass) {
                    const uint32_t* wp = wf + (size_t)(((pass * 32 + kt) * 4) * 32 + lane) * 2;
#pragma unroll
                    for (int nt = 0; nt < 4; ++nt) {
                        mma16816(acc[nt], a0, a1, a2, a3, wp[nt * 64], wp[nt * 64 + 1]);
                    }
                }
            }
            __syncwarp();
            if (lane == 0) mbar_arrive(mb + 128 + qt * 8);   // A buffer consumed

            if (sp > 0) { mbar_wait(mb + 168, ph_free); ph_free ^= 1; }

            {
                float* ex = exch + kq * (32 * 29);
#pragma unroll
                for (int nt = 0; nt < 4; ++nt) {
#pragma unroll
                    for (int q = 0; q < 4; ++q) {
                        int row = mt * 16 + grp + ((q >> 1) * 8);
                        int n   = nt * 8 + tg4 * 2 + (q & 1);
                        ex[row * 29 + n] = acc[nt][q];
                    }
                }
            }
            __syncwarp();
            if (lane == 0) mbar_arrive(mb + 160);            // exch ready (16 arrivals)
        }
    }
}

// =====================  launch  =====================
extern "C" void kernel_launch(void* const* d_in, const int* in_sizes, int n_in,
                              void* d_out, int out_size)
{
    const int*   marks = (const int*)  d_in[0];
    const float* ts    = (const float*)d_in[1];
    const float* emb   = (const float*)d_in[2];
    const float* Wc    = (const float*)d_in[3];
    const float* bc    = (const float*)d_in[4];
    const float* init  = (const float*)d_in[5];
    float*       out   = (float*)d_out;

    dim3 g1(G7 / 256, (C_ + 15) / 16);
    tg_kernel<<<g1, 256>>>(emb, Wc, bc);

    cudaFuncSetAttribute(rec_kernel, cudaFuncAttributeMaxDynamicSharedMemorySize, SMEM_BYTES);
    rec_kernel<<<NCTA, NTHR, SMEM_BYTES>>>(marks, ts, Wc, init, out);
}

// round 17
// speedup vs baseline: 1.5512x; 1.5512x over previous
#include <cuda_runtime.h>
#include <cuda_bf16.h>
#include <cstdint>

#define B_   64
#define T_   512
#define H_   512
#define E_   128
#define C_   1000
#define G7   (7 * H_)    // 3584
#define OUTW (6 * H_)    // 3072
#define NCTA 128
#define NTHR 544         // 16 consumer warps + 1 producer warp

typedef unsigned long long ull;

// ---- device-global scratch ----
__device__ float g_tg[C_ * G7];                          // table_gates (14.3 MB)
__device__ __align__(128) unsigned char g_himg[2][2][65536];  // [half][parity] A-image (fragment order)
__device__ int           g_count;
__device__ volatile int  g_sense;
__device__ int           g_cnt[8];                       // [half*4 + group] cumulative publish counters

// ---- math helpers ----
__device__ __forceinline__ float sigf(float x)      { return 1.0f / (1.0f + expf(-x)); }
__device__ __forceinline__ float softplusf(float x) { return fmaxf(x, 0.0f) + log1pf(expf(-fabsf(x))); }

__device__ __forceinline__ uint32_t smem_u32(const void* p)
{
    uint32_t a;
    asm("{ .reg .u64 t; cvta.to.shared.u64 t, %1; cvt.u32.u64 %0, t; }" : "=r"(a) : "l"(p));
    return a;
}
__device__ __forceinline__ int ld_acq(const int* p)
{
    int v;
    asm volatile("ld.acquire.gpu.global.s32 %0, [%1];" : "=r"(v) : "l"(p) : "memory");
    return v;
}
__device__ __forceinline__ void mbar_init(uint32_t mbar, uint32_t cnt)
{
    asm volatile("mbarrier.init.shared.b64 [%0], %1;" :: "r"(mbar), "r"(cnt) : "memory");
}
__device__ __forceinline__ void mbar_expect_tx(uint32_t mbar, uint32_t bytes)
{
    asm volatile("mbarrier.arrive.expect_tx.shared.b64 _, [%0], %1;" :: "r"(mbar), "r"(bytes) : "memory");
}
__device__ __forceinline__ void mbar_arrive(uint32_t mbar)
{
    asm volatile("mbarrier.arrive.release.cta.shared::cta.b64 _, [%0];" :: "r"(mbar) : "memory");
}
__device__ __forceinline__ void bulk_ldgsts(uint32_t dst, const void* src, uint32_t bytes, uint32_t mbar)
{
    asm volatile("cp.async.bulk.shared::cta.global.mbarrier::complete_tx::bytes [%0], [%1], %2, [%3];"
                 :: "r"(dst), "l"(src), "r"(bytes), "r"(mbar) : "memory");
}
__device__ __forceinline__ void mbar_wait(uint32_t mbar, uint32_t parity)
{
    uint32_t done;
    asm volatile(
        "{\n\t.reg .pred p;\n\t"
        "mbarrier.try_wait.parity.acquire.cta.shared::cta.b64 p, [%1], %2;\n\t"
        "selp.b32 %0, 1, 0, p;\n\t}"
        : "=r"(done) : "r"(mbar), "r"(parity) : "memory");
    if (!done) {
        asm volatile(
            "{\n\t.reg .pred P1;\n\t"
            "WL_%=:\n\t"
            "mbarrier.try_wait.parity.acquire.cta.shared::cta.b64 P1, [%0], %1, 0x989680;\n\t"
            "@P1 bra.uni WD_%=;\n\t"
            "bra.uni WL_%=;\n\t"
            "WD_%=:\n\t}"
            :: "r"(mbar), "r"(parity) : "memory");
    }
}
__device__ __forceinline__ void fence_proxy_async_()
{
    asm volatile("fence.proxy.async;" ::: "memory");
}

// bf16 mma.sync (baseline PTX, sm_80+)
__device__ __forceinline__ void mma16816(float* d,
                                         uint32_t a0, uint32_t a1, uint32_t a2, uint32_t a3,
                                         uint32_t b0, uint32_t b1)
{
    asm volatile(
        "mma.sync.aligned.m16n8k16.row.col.f32.bf16.bf16.f32 "
        "{%0,%1,%2,%3}, {%4,%5,%6,%7}, {%8,%9}, {%0,%1,%2,%3};"
        : "+f"(d[0]), "+f"(d[1]), "+f"(d[2]), "+f"(d[3])
        : "r"(a0), "r"(a1), "r"(a2), "r"(a3), "r"(b0), "r"(b1));
}

// ---- smem layout (bytes) ----
#define A0_OFF     0                  // half0 A buffer: 64KB
#define A1_OFF     65536              // half1 A buffer: 64KB
#define WF_OFF     131072             // W fragments: 64KB
#define EXCH_OFF   196608             // 4 x 64 x 29 fp32 = 29696
#define MBAR_OFF   226304             // full[2][4] + consumed[2] + ready + free
#define SMEM_BYTES (MBAR_OFF + 128)   // 226432

// half A-image offset for element (m in 0..63, k in 0..511); chunk c = kt in [8c,8c+8) = 16KB
__device__ __forceinline__ uint32_t aimg_off(int m, int k)
{
    int mt = m >> 4, mr = m & 15;
    int kt = k >> 4, kr = k & 15;
    int lane = ((mr & 7) << 2) | ((kr >> 1) & 3);
    int reg  = ((mr >> 3) & 1) | ((kr & 8) ? 2 : 0);
    return ((((uint32_t)(kt * 4 + mt) * 32 + lane) * 4 + reg) * 4) + ((kr & 1) * 2);
}

// atomic grid sync (init only; called twice -> even parity per launch, replay safe)
__device__ __forceinline__ void grid_sync_init(int* sense)
{
    __threadfence();
    __syncthreads();
    if (threadIdx.x == 0) {
        int s = *sense ^ 1;
        *sense = s;
        if (atomicAdd(&g_count, 1) == (int)gridDim.x - 1) {
            g_count = 0;
            __threadfence();
            g_sense = s;
        } else {
            while (g_sense != s) { __nanosleep(64); }
            __threadfence();
        }
    }
    __syncthreads();
}

// =====================  Kernel 1: table_gates  =====================
__global__ void tg_kernel(const float* __restrict__ emb,
                          const float* __restrict__ W,
                          const float* __restrict__ bias)
{
    __shared__ float sh_e[16][E_];
    const int col = blockIdx.x * 256 + threadIdx.x;
    const int c0  = blockIdx.y * 16;

    for (int i = threadIdx.x; i < 16 * E_; i += 256) {
        int ci = i >> 7, e = i & 127;
        int c  = c0 + ci;
        sh_e[ci][e] = (c < C_) ? emb[c * E_ + e] : 0.0f;
    }
    __syncthreads();

    float acc[16];
#pragma unroll
    for (int i = 0; i < 16; ++i) acc[i] = 0.0f;

    for (int e = 0; e < E_; ++e) {
        float wv = W[e * G7 + col];
#pragma unroll
        for (int i = 0; i < 16; ++i) acc[i] = fmaf(sh_e[i][e], wv, acc[i]);
    }
    float bb = bias[col];
#pragma unroll
    for (int i = 0; i < 16; ++i) {
        int c = c0 + i;
        if (c < C_) g_tg[c * G7 + col] = acc[i] + bb;
    }
}

// =====================  Kernel 2: persistent HMMA, mbarrier dataflow (no block barriers)  =====================
// 128 CTAs x 544 threads. Consumer warps 0..15: mt = wid & 3, kq = wid >> 2 (kq == chunk id).
// Producer thread 512: polls counters, issues TMA. Epilogue = warps 0..3 (tid<128).
// mbarriers: full[buf][c] = mb+(buf*4+c)*8 ; consumed[buf] = mb+64+8*buf ;
//            exch_ready = mb+80 (16 warp-leader arrivals) ; exch_free = mb+88 (128 arrivals).
__global__ void __launch_bounds__(NTHR, 1)
rec_kernel(const int*   __restrict__ marks,
           const float* __restrict__ ts,
           const float* __restrict__ Wc,
           const float* __restrict__ init,
           float*       __restrict__ out)
{
    extern __shared__ unsigned char smem[];
    uint32_t*      wf   = (uint32_t*)(smem + WF_OFF);
    float*         exch = (float*)(smem + EXCH_OFF);     // [kq4][64][29]
    const uint32_t mb   = smem_u32(smem + MBAR_OFF);
    const uint32_t smA0 = smem_u32(smem + A0_OFF);

    const int tid  = threadIdx.x;
    const int cta  = blockIdx.x;
    const int lane = tid & 31;
    const int wid  = tid >> 5;
    const int mt   = wid & 3;        // consumer: mtile 0..3
    const int kq   = wid >> 2;       // consumer: chunk 0..3 (wid<16)
    const int grp  = lane >> 2;
    const int tg4  = lane & 3;

    const int eb32 = tid >> 2;       // epilogue local batch (tid < 128)
    const int ejl  = tid & 3;
    const int ej   = cta * 4 + ejl;

    if (tid == 0) {
#pragma unroll
        for (int i = 0; i < 8; ++i) mbar_init(mb + i * 8, 1);       // full barriers
        mbar_init(mb + 64, 16);                                     // consumed[0]
        mbar_init(mb + 72, 16);                                     // consumed[1]
        mbar_init(mb + 80, 16);                                     // exch_ready (warp leaders)
        mbar_init(mb + 88, 128);                                    // exch_free (epilogue threads)
    }
    if (cta == 0 && tid < 8) g_cnt[tid] = 0;

    // ---- prepack W fragments (hi pass 0 / lo pass 1), B-fragment order ----
    for (int idx = tid; idx < 8192; idx += NTHR) {
        int l    = idx & 31;
        int nt   = (idx >> 5) & 3;
        int kt   = (idx >> 7) & 31;
        int pass = idx >> 12;
        int n    = nt * 8 + (l >> 2);
        int k0   = kt * 16 + (l & 3) * 2;
        float w[4];
#pragma unroll
        for (int i = 0; i < 4; ++i) {
            int k = k0 + (i & 1) + ((i >> 1) * 8);
            float v = 0.0f;
            if (n < 28) v = Wc[(size_t)(E_ + k) * G7 + (n >> 2) * H_ + cta * 4 + (n & 3)];
            if (pass == 0) w[i] = __bfloat162float(__float2bfloat16(v));
            else           w[i] = v - __bfloat162float(__float2bfloat16(v));
        }
        __nv_bfloat162 r0, r1;
        r0.x = __float2bfloat16(w[0]); r0.y = __float2bfloat16(w[1]);
        r1.x = __float2bfloat16(w[2]); r1.y = __float2bfloat16(w[3]);
        wf[idx * 2]     = *(uint32_t*)&r0;
        wf[idx * 2 + 1] = *(uint32_t*)&r1;
    }

    // ---- init h images t=0 (this CTA's 4 k columns; both halves, hi+lo rows) ----
    for (int idx = tid; idx < 512; idx += NTHR) {
        int b    = idx >> 3;
        int jj   = (idx >> 1) & 3;
        int hilo = idx & 1;
        int k    = cta * 4 + jj;
        float v  = tanhf(init[k]);
        __nv_bfloat16 hi = __float2bfloat16(v);
        __nv_bfloat16 val = hilo ? __float2bfloat16(v - __bfloat162float(hi)) : hi;
        int half = b >> 5;
        int m    = (b & 31) + hilo * 32;
        *(__nv_bfloat16*)(g_himg[half][0] + aimg_off(m, k)) = val;
    }

    // ---- output row t=0 ----
    for (int idx = tid; idx < 4 * 6 * 64; idx += NTHR) {
        int bb = idx & 63; int rest = idx >> 6;
        int f = rest % 6; int jj = rest / 6;
        int jg = cta * 4 + jj;
        float v;
        switch (f) {
            case 0:  v = tanhf(init[0 * H_ + jg]);     break;
            case 1:  v = sigf (init[5 * H_ + jg]);     break;
            case 2:  v = tanhf(init[2 * H_ + jg]);     break;
            case 3:  v = tanhf(init[3 * H_ + jg]);     break;
            case 4:  v = softplusf(init[4 * H_ + jg]); break;
            default: v = tanhf(init[1 * H_ + jg]);     break;
        }
        out[(size_t)bb * (513 * OUTW) + f * H_ + jg] = v;
    }

    // ---- per-(b,j) recurrent state (epilogue threads) ----
    float cdv[2], cbv[2];
    cdv[0] = cdv[1] = tanhf(init[H_ + ej]);
    cbv[0] = cbv[1] = tanhf(init[2 * H_ + ej]);

    const uint32_t off_hi = aimg_off(eb32, ej);
    const uint32_t off_lo = aimg_off(eb32 + 32, ej);

    // ---- two init grid syncs (h0/counters visible; even parity) ----
    int sense = 0;
    grid_sync_init(&sense);
    grid_sync_init(&sense);

    if (tid >= 513) return;

    // =====================  producer thread (tid 512)  =====================
    if (tid == 512) {
        int phc[2] = {0, 0};
        fence_proxy_async_();
#pragma unroll
        for (int c = 0; c < 4; ++c) {
            mbar_expect_tx(mb + c * 8, 16384);
            bulk_ldgsts(smA0 + c * 16384, g_himg[0][0] + c * 16384, 16384, mb + c * 8);
        }
#pragma unroll
        for (int c = 0; c < 4; ++c) {
            mbar_expect_tx(mb + (4 + c) * 8, 16384);
            bulk_ldgsts(smA0 + 65536 + c * 16384, g_himg[1][0] + c * 16384, 16384, mb + (4 + c) * 8);
        }
        for (int sp = 2; sp < 1024; ++sp) {
            const int buf = sp & 1;
            const int t   = sp >> 1;
            mbar_wait(mb + 64 + buf * 8, phc[buf]); phc[buf] ^= 1;   // consumers done with buffer
            const int need = 128 * t;                                // 4 warp-bumps per CTA per step
#pragma unroll
            for (int c = 0; c < 4; ++c) {
                while (ld_acq(&g_cnt[buf * 4 + c]) < need) { __nanosleep(32); }
            }
            fence_proxy_async_();
            const unsigned char* src = g_himg[buf][t & 1];
            const uint32_t dstb = smA0 + buf * 65536;
#pragma unroll
            for (int c = 0; c < 4; ++c) {
                mbar_expect_tx(mb + (buf * 4 + c) * 8, 16384);
                bulk_ldgsts(dstb + c * 16384, src + c * 16384, 16384, mb + (buf * 4 + c) * 8);
            }
        }
        return;
    }

    // =====================  consumer warps (tid < 512)  =====================
    int fph[2]   = {0, 0};
    int ph_free  = 0;     // exch_free wait parity (MMA side)
    int ph_ready = 0;     // exch_ready wait parity (epilogue side)
    int spg      = 0;

    for (int t = 0; t < T_; ++t) {
#pragma unroll
        for (int half = 0; half < 2; ++half) {
            const int buf = half;
            const uint32_t abuf = smA0 + buf * 65536;

            // ---- epilogue prefetch (independent long-latency loads) ----
            float tsv = 0.f, tsp = 0.f, tgv[7];
            if (tid < 128) {
                int b = half * 32 + eb32;
                int mk = __ldg(&marks[b * T_ + t]);
                tsv = __ldg(&ts[b * T_ + t]);
                tsp = (t > 0) ? __ldg(&ts[b * T_ + t - 1]) : 0.0f;
                const float* tgp = g_tg + (size_t)mk * G7 + ej;
#pragma unroll
                for (int g = 0; g < 7; ++g) tgv[g] = __ldcg(tgp + g * H_);
            }

            // ---- MMA: warp (kq, mt) waits only its own chunk ----
            float acc[4][4];
#pragma unroll
            for (int j = 0; j < 4; ++j)
#pragma unroll
                for (int q = 0; q < 4; ++q) acc[j][q] = 0.0f;

            mbar_wait(mb + (buf * 4 + kq) * 8, fph[buf]);
            fph[buf] ^= 1;

            const uint32_t abase = abuf + ((uint32_t)mt * 32 + lane) * 16;
#pragma unroll
            for (int kti = 0; kti < 8; ++kti) {
                const int kt = kq * 8 + kti;
                uint32_t a0, a1, a2, a3;
                asm volatile("ld.shared.v4.b32 {%0,%1,%2,%3}, [%4];"
                             : "=r"(a0), "=r"(a1), "=r"(a2), "=r"(a3)
                             : "r"(abase + (uint32_t)kt * 2048));
#pragma unroll
                for (int pass = 0; pass < 2; ++pass) {
                    const uint32_t* wp = wf + (size_t)(((pass * 32 + kt) * 4) * 32 + lane) * 2;
#pragma unroll
                    for (int nt = 0; nt < 4; ++nt) {
                        mma16816(acc[nt], a0, a1, a2, a3, wp[nt * 64], wp[nt * 64 + 1]);
                    }
                }
            }
            __syncwarp();
            if (lane == 0) mbar_arrive(mb + 64 + buf * 8);   // A buffer consumed

            // ---- exch 1-deep throttle, then store D fragments ----
            if (spg > 0) { mbar_wait(mb + 88, ph_free); ph_free ^= 1; }
            {
                float* ex = exch + kq * (64 * 29);
#pragma unroll
                for (int nt = 0; nt < 4; ++nt) {
#pragma unroll
                    for (int q = 0; q < 4; ++q) {
                        int row = mt * 16 + grp + ((q >> 1) * 8);
                        int n   = nt * 8 + tg4 * 2 + (q & 1);
                        ex[row * 29 + n] = acc[nt][q];
                    }
                }
            }
            __syncwarp();
            if (lane == 0) mbar_arrive(mb + 80);             // exch ready (16 leaders)

            // ---- epilogue (warps 0-3 only): read -> free -> gates -> publish -> counter ----
            if (tid < 128) {
                mbar_wait(mb + 80, ph_ready);

                float a[7];
#pragma unroll
                for (int g = 0; g < 7; ++g) {
                    int n = g * 4 + ejl;
                    float s = 0.f;
#pragma unroll
                    for (int q2 = 0; q2 < 4; ++q2)
                        s += exch[q2 * (64 * 29) + eb32 * 29 + n]
                           + exch[q2 * (64 * 29) + (eb32 + 32) * 29 + n];
                    a[g] = s;
                }
                mbar_arrive(mb + 88);        // exch free (128 arrivals)

                float dur = tsv - tsp;
                float gi  = sigf (a[0] + tgv[0]);
                float gf  = sigf (a[1] + tgv[1]);
                float gz  = tanhf(a[2] + tgv[2]);
                float go  = sigf (a[3] + tgv[3]);
                float gib = sigf (a[4] + tgv[4]);
                float gfb = sigf (a[5] + tgv[5]);
                float gd  = softplusf(a[6] + tgv[6]);

                float cx  = gf * cdv[half] + gi * gz;
                float cbx = gfb * cbv[half] + gib * gz;
                float cd  = cbx + (cx - cbx) * expf(-gd * dur);
                float hd  = go * tanhf(cd);
                cdv[half] = cd; cbv[half] = cbx;

                __nv_bfloat16 hi = __float2bfloat16(hd);
                __nv_bfloat16 lo = __float2bfloat16(hd - __bfloat162float(hi));
                unsigned char* dst = g_himg[half][(t + 1) & 1];
                *(__nv_bfloat16*)(dst + off_hi) = hi;
                *(__nv_bfloat16*)(dst + off_lo) = lo;

                __threadfence();
                __syncwarp();
                if (lane == 0) atomicAdd(&g_cnt[half * 4 + (cta >> 5)], 1);  // per-warp bump

                // off critical path: fp32 outputs
                int b = half * 32 + eb32;
                size_t ob = (size_t)b * (513 * OUTW) + (size_t)(t + 1) * OUTW + ej;
                out[ob]          = hd;
                out[ob + 1 * H_] = go;
                out[ob + 2 * H_] = cbx;
                out[ob + 3 * H_] = cx;
                out[ob + 4 * H_] = gd;
                out[ob + 5 * H_] = cd;
            }
            ph_ready ^= 1;
            ++spg;
        }
    }
}

// =====================  launch  =====================
extern "C" void kernel_launch(void* const* d_in, const int* in_sizes, int n_in,
                              void* d_out, int out_size)
{
    const int*   marks = (const int*)  d_in[0];
    const float* ts    = (const float*)d_in[1];
    const float* emb   = (const float*)d_in[2];
    const float* Wc    = (const float*)d_in[3];
    const float* bc    = (const float*)d_in[4];
    const float* init  = (const float*)d_in[5];
    float*       out   = (float*)d_out;

    dim3 g1(G7 / 256, (C_ + 15) / 16);
    tg_kernel<<<g1, 256>>>(emb, Wc, bc);

    cudaFuncSetAttribute(rec_kernel, cudaFuncAttributeMaxDynamicSharedMemorySize, SMEM_BYTES);
    rec_kernel<<<NCTA, NTHR, SMEM_BYTES>>>(marks, ts, Wc, init, out);
}